// round 1
// baseline (speedup 1.0000x reference)
#include <cuda_runtime.h>
#include <math.h>

// Problem dims (fixed by reference setup_inputs)
#define BATCH 4096
#define DIN   256
#define H1DIM 512
#define H2DIM 512
#define DOUT  256
#define G2    16
#define G3    8
#define BN_EPS 1e-5f

// ---------------- scratch (static device allocations; no cudaMalloc) ----------------
__device__ float g_Hpre[BATCH * H1DIM];          // layer1 pre-BN output      (8 MB)
__device__ float g_C1[H1DIM * BATCH];            // cos(a) seeds, [i][n]      (8 MB)
__device__ float g_S1[H1DIM * BATCH];            // sin(a) seeds, [i][n]      (8 MB)
__device__ float g_H2[BATCH * H2DIM];            // layer2 output             (8 MB)
__device__ float g_C2[H2DIM * BATCH];            // layer3 seeds              (8 MB)
__device__ float g_S2[H2DIM * BATCH];            //                           (8 MB)
__device__ float g_B2[H1DIM * 2 * G2 * H2DIM];   // coeffs2 transposed [i][k][o] (32 MB)
__device__ float g_B3[H2DIM * 2 * G3 * DOUT];    // coeffs3 transposed [i][k][o] (8 MB)
__device__ float g_H3[BATCH * DOUT];             // logits                    (4 MB)
__device__ float g_part[512];                    // partial sums (sum, sumsq)
__device__ float g_ss[2];                        // BN scale, shift

// ---------------- K0: coeff layout transform ----------------
// in:  [2][O][I][G] row-major   out: [(i*2G + t*G + g)][O]
__global__ void transpose_coeffs(const float* __restrict__ in, float* __restrict__ out,
                                 int O, int I, int G) {
    __shared__ float tile[32][33];
    const int t  = blockIdx.z;
    const int ig0 = blockIdx.x * 32;
    const int o0  = blockIdx.y * 32;
    const int IG = I * G;
    const int tx = threadIdx.x, ty = threadIdx.y;
    #pragma unroll
    for (int r = 0; r < 32; r += 8) {
        int o = o0 + ty + r;
        tile[ty + r][tx] = in[(size_t)(t * O + o) * IG + ig0 + tx];
    }
    __syncthreads();
    #pragma unroll
    for (int r = 0; r < 32; r += 8) {
        int ig = ig0 + ty + r;
        int i = ig / G, g = ig % G;
        int krow = i * 2 * G + t * G + g;
        out[(size_t)krow * O + o0 + tx] = tile[tx][ty + r];
    }
}

// ---------------- K1: layer1 GEMM  Hpre[n][o] = x[n]·W1[o] + b1[o] ----------------
__global__ __launch_bounds__(256) void gemm1(const float* __restrict__ x,
                                             const float* __restrict__ W1,
                                             const float* __restrict__ b1,
                                             float* __restrict__ out) {
    __shared__ __align__(16) float As[16][68];
    __shared__ __align__(16) float Bs[16][68];
    const int tid = threadIdx.x;
    const int tx = tid & 15, ty = tid >> 4;
    const int n0 = blockIdx.x * 64, o0 = blockIdx.y * 64;
    float acc[4][4] = {};
    for (int k0 = 0; k0 < DIN; k0 += 16) {
        __syncthreads();
        #pragma unroll
        for (int lin = tid; lin < 1024; lin += 256) {
            int k = lin & 15, m = lin >> 4;
            As[k][m] = x[(n0 + m) * DIN + k0 + k];
            Bs[k][m] = W1[(o0 + m) * DIN + k0 + k];
        }
        __syncthreads();
        #pragma unroll
        for (int kk = 0; kk < 16; kk++) {
            float a[4], b[4];
            #pragma unroll
            for (int j = 0; j < 4; j++) { a[j] = As[kk][ty * 4 + j]; b[j] = Bs[kk][tx * 4 + j]; }
            #pragma unroll
            for (int im = 0; im < 4; im++)
                #pragma unroll
                for (int io = 0; io < 4; io++)
                    acc[im][io] += a[im] * b[io];
        }
    }
    #pragma unroll
    for (int im = 0; im < 4; im++) {
        int n = n0 + ty * 4 + im;
        #pragma unroll
        for (int io = 0; io < 4; io++) {
            int o = o0 + tx * 4 + io;
            out[n * H1DIM + o] = acc[im][io] + b1[o];
        }
    }
}

// ---------------- K2: deterministic BN stats ----------------
__global__ void reduce_stats() {
    __shared__ float ss[256], sq[256];
    const int tid = threadIdx.x;
    float s = 0.f, q = 0.f;
    for (int i = blockIdx.x * 256 + tid; i < BATCH * H1DIM; i += 256 * 256) {
        float v = g_Hpre[i];
        s += v; q += v * v;
    }
    ss[tid] = s; sq[tid] = q;
    __syncthreads();
    for (int off = 128; off; off >>= 1) {
        if (tid < off) { ss[tid] += ss[tid + off]; sq[tid] += sq[tid + off]; }
        __syncthreads();
    }
    if (tid == 0) { g_part[blockIdx.x] = ss[0]; g_part[256 + blockIdx.x] = sq[0]; }
}

__global__ void finalize_stats(const float* __restrict__ gamma, const float* __restrict__ beta) {
    __shared__ float ss[256], sq[256];
    const int tid = threadIdx.x;
    ss[tid] = g_part[tid]; sq[tid] = g_part[256 + tid];
    __syncthreads();
    for (int off = 128; off; off >>= 1) {
        if (tid < off) { ss[tid] += ss[tid + off]; sq[tid] += sq[tid + off]; }
        __syncthreads();
    }
    if (tid == 0) {
        const float inv_n = 1.0f / (float)(BATCH * H1DIM);
        float mean = ss[0] * inv_n;
        float var  = sq[0] * inv_n - mean * mean;
        float sc = gamma[0] * rsqrtf(var + BN_EPS);
        g_ss[0] = sc;
        g_ss[1] = beta[0] - mean * sc;
    }
}

// ---------------- K3: (optional BN+ReLU) -> cos/sin seed, transposed to [i][n] ----------------
__global__ void basis_seed(const float* __restrict__ src, float* __restrict__ Cd,
                           float* __restrict__ Sd, int useBN) {
    __shared__ float tc[32][33], tsn[32][33];
    const int i0 = blockIdx.x * 32, n0 = blockIdx.y * 32;
    const int tx = threadIdx.x, ty = threadIdx.y;
    float sc = 1.f, sh = 0.f;
    if (useBN) { sc = g_ss[0]; sh = g_ss[1]; }
    #pragma unroll
    for (int r = 0; r < 32; r += 8) {
        float v = src[(n0 + ty + r) * 512 + i0 + tx];
        v = sc * v + sh;
        if (useBN) v = fmaxf(v, 0.f);
        tc[ty + r][tx]  = cosf(v);
        tsn[ty + r][tx] = sinf(v);
    }
    __syncthreads();
    #pragma unroll
    for (int r = 0; r < 32; r += 8) {
        Cd[(i0 + ty + r) * BATCH + n0 + tx] = tc[tx][ty + r];
        Sd[(i0 + ty + r) * BATCH + n0 + tx] = tsn[tx][ty + r];
    }
}

// ---------------- K4/K5: Fourier-KAN GEMM ----------------
// out[n][o] = bias[o] + sum_i sum_g cos((g+1)a_ni)*C0[o,i,g] + sin((g+1)a_ni)*C1[o,i,g]
// Harmonics generated in smem via angle-addition recurrence from (cos a, sin a) seeds.
// Block tile: 128(M) x 64(N), 256 threads, 8x4 per thread. K per feature = KPF = 2*grid.
template <int KPF, int NOUT>
__global__ __launch_bounds__(256) void kan_gemm(const float* __restrict__ Cseed,
                                                const float* __restrict__ Sseed,
                                                const float* __restrict__ Bmat,
                                                const float* __restrict__ bias,
                                                float* __restrict__ out) {
    constexpr int G = KPF / 2;
    __shared__ __align__(16) float basisT[KPF][132];
    __shared__ __align__(16) float Bs[KPF][68];
    const int tid = threadIdx.x;
    const int tx = tid & 15, ty = tid >> 4;
    const int n0 = blockIdx.x * 128, o0 = blockIdx.y * 64;
    float acc[8][4] = {};
    float c1 = 0.f, s1 = 0.f;
    if (tid < 128) { c1 = Cseed[n0 + tid]; s1 = Sseed[n0 + tid]; }  // feature 0 seed

    for (int i = 0; i < 512; i++) {
        __syncthreads();
        if (tid < 128) {
            float c = c1, s = s1;
            #pragma unroll
            for (int g = 0; g < G; g++) {
                basisT[g][tid]     = c;   // cos((g+1)a)
                basisT[G + g][tid] = s;   // sin((g+1)a)
                float cn = c * c1 - s * s1;
                float sn = s * c1 + c * s1;
                c = cn; s = sn;
            }
            if (i + 1 < 512) {            // prefetch next feature's seed
                c1 = Cseed[(i + 1) * BATCH + n0 + tid];
                s1 = Sseed[(i + 1) * BATCH + n0 + tid];
            }
        }
        #pragma unroll
        for (int r = 0; r < (KPF * 64) / 256; r++) {
            int lin = r * 256 + tid;
            int k = lin >> 6, o = lin & 63;
            Bs[k][o] = Bmat[(size_t)(i * KPF + k) * NOUT + o0 + o];
        }
        __syncthreads();
        #pragma unroll 8
        for (int kk = 0; kk < KPF; kk++) {
            float4 a0 = *(const float4*)&basisT[kk][ty * 8];
            float4 a1 = *(const float4*)&basisT[kk][ty * 8 + 4];
            float4 b  = *(const float4*)&Bs[kk][tx * 4];
            float am[8] = {a0.x, a0.y, a0.z, a0.w, a1.x, a1.y, a1.z, a1.w};
            float bv[4] = {b.x, b.y, b.z, b.w};
            #pragma unroll
            for (int im = 0; im < 8; im++)
                #pragma unroll
                for (int io = 0; io < 4; io++)
                    acc[im][io] += am[im] * bv[io];
        }
    }
    float bb[4];
    #pragma unroll
    for (int io = 0; io < 4; io++) bb[io] = bias[o0 + tx * 4 + io];
    #pragma unroll
    for (int im = 0; im < 8; im++) {
        int n = n0 + ty * 8 + im;
        #pragma unroll
        for (int io = 0; io < 4; io++)
            out[(size_t)n * NOUT + o0 + tx * 4 + io] = acc[im][io] + bb[io];
    }
}

// ---------------- K6: softmax over DOUT ----------------
__global__ void softmax_k(const float* __restrict__ in, float* __restrict__ out) {
    __shared__ float red[256];
    const int row = blockIdx.x, tid = threadIdx.x;
    float v = in[row * DOUT + tid];
    red[tid] = v;
    __syncthreads();
    for (int off = 128; off; off >>= 1) {
        if (tid < off) red[tid] = fmaxf(red[tid], red[tid + off]);
        __syncthreads();
    }
    float mx = red[0];
    __syncthreads();
    float e = expf(v - mx);
    red[tid] = e;
    __syncthreads();
    for (int off = 128; off; off >>= 1) {
        if (tid < off) red[tid] += red[tid + off];
        __syncthreads();
    }
    out[row * DOUT + tid] = e / red[0];
}

// ---------------- launch ----------------
extern "C" void kernel_launch(void* const* d_in, const int* in_sizes, int n_in,
                              void* d_out, int out_size) {
    const float* x       = (const float*)d_in[0];
    const float* W1      = (const float*)d_in[1];
    const float* b1      = (const float*)d_in[2];
    const float* gamma   = (const float*)d_in[3];
    const float* beta    = (const float*)d_in[4];
    const float* coeffs2 = (const float*)d_in[5];
    const float* bias2   = (const float*)d_in[6];
    const float* coeffs3 = (const float*)d_in[7];
    const float* bias3   = (const float*)d_in[8];
    float* out = (float*)d_out;

    float *pHpre, *pC1, *pS1, *pH2, *pC2, *pS2, *pB2, *pB3, *pH3;
    cudaGetSymbolAddress((void**)&pHpre, g_Hpre);
    cudaGetSymbolAddress((void**)&pC1, g_C1);
    cudaGetSymbolAddress((void**)&pS1, g_S1);
    cudaGetSymbolAddress((void**)&pH2, g_H2);
    cudaGetSymbolAddress((void**)&pC2, g_C2);
    cudaGetSymbolAddress((void**)&pS2, g_S2);
    cudaGetSymbolAddress((void**)&pB2, g_B2);
    cudaGetSymbolAddress((void**)&pB3, g_B3);
    cudaGetSymbolAddress((void**)&pH3, g_H3);

    // coeff layout transforms (recomputed every call; deterministic)
    transpose_coeffs<<<dim3((512 * G2) / 32, H2DIM / 32, 2), dim3(32, 8)>>>(coeffs2, pB2, H2DIM, H1DIM, G2);
    transpose_coeffs<<<dim3((512 * G3) / 32, DOUT / 32, 2), dim3(32, 8)>>>(coeffs3, pB3, DOUT, H2DIM, G3);

    // layer 1
    gemm1<<<dim3(BATCH / 64, H1DIM / 64), 256>>>(x, W1, b1, pHpre);

    // batchnorm stats (deterministic two-stage)
    reduce_stats<<<256, 256>>>();
    finalize_stats<<<1, 256>>>(gamma, beta);

    // layer 2: seeds (BN+ReLU fused) then KAN GEMM
    basis_seed<<<dim3(H1DIM / 32, BATCH / 32), dim3(32, 8)>>>(pHpre, pC1, pS1, 1);
    kan_gemm<2 * G2, H2DIM><<<dim3(BATCH / 128, H2DIM / 64), 256>>>(pC1, pS1, pB2, bias2, pH2);

    // layer 3: seeds (identity) then KAN GEMM
    basis_seed<<<dim3(H2DIM / 32, BATCH / 32), dim3(32, 8)>>>(pH2, pC2, pS2, 0);
    kan_gemm<2 * G3, DOUT><<<dim3(BATCH / 128, DOUT / 64), 256>>>(pC2, pS2, pB3, bias3, pH3);

    // softmax
    softmax_k<<<BATCH, 256>>>(pH3, out);
}

// round 7
// speedup vs baseline: 2.5588x; 2.5588x over previous
#include <cuda_runtime.h>
#include <cuda_bf16.h>
#include <math.h>
#include <stdint.h>

// Problem dims (fixed by reference setup_inputs)
#define BATCH 4096
#define DIN   256
#define H1DIM 512
#define H2DIM 512
#define DOUT  256
#define G2    16
#define G3    8
#define BN_EPS 1e-5f

// ---------------- scratch (static device allocations; no cudaMalloc) ----------------
__device__ float g_Hpre[BATCH * H1DIM];          // layer1 pre-BN output
__device__ float g_C1[H1DIM * BATCH];            // cos(a) seeds, [i][n]
__device__ float g_S1[H1DIM * BATCH];            // sin(a) seeds, [i][n]
__device__ float g_H2[BATCH * H2DIM];            // layer2 output
__device__ float g_C2[H2DIM * BATCH];            // layer3 seeds
__device__ float g_S2[H2DIM * BATCH];
__device__ float g_B2[(size_t)H1DIM * 2 * G2 * H2DIM];  // coeffs2 [i*2G+t*G+g][o], tf32-rounded
__device__ float g_B3[(size_t)H2DIM * 2 * G3 * DOUT];   // coeffs3 same layout
__device__ float g_H3[BATCH * DOUT];             // logits
__device__ float g_part[512];                    // partial sums (sum, sumsq)
__device__ float g_ss[2];                        // BN scale, shift

// ---------------- helpers ----------------
__device__ __forceinline__ float to_tf32(float x) {
    float r;
    asm("cvt.rna.tf32.f32 %0, %1;" : "=f"(r) : "f"(x));
    return r;
}
__device__ __forceinline__ void mma_tf32(float& c0, float& c1, float& c2, float& c3,
                                         uint32_t a0, uint32_t a1, uint32_t a2, uint32_t a3,
                                         uint32_t b0, uint32_t b1) {
    asm volatile(
        "mma.sync.aligned.m16n8k8.row.col.f32.tf32.tf32.f32 "
        "{%0,%1,%2,%3}, {%4,%5,%6,%7}, {%8,%9}, {%0,%1,%2,%3};"
        : "+f"(c0), "+f"(c1), "+f"(c2), "+f"(c3)
        : "r"(a0), "r"(a1), "r"(a2), "r"(a3), "r"(b0), "r"(b1));
}

// ---------------- K0: coeff layout transform (+ tf32 rounding) ----------------
// in:  [2][O][I][G] row-major   out: [(i*2G + t*G + g)][O]  fp32 (tf32-rounded)
__global__ void transpose_coeffs(const float* __restrict__ in, float* __restrict__ out,
                                 int O, int I, int G) {
    __shared__ float tile[32][33];
    const int t  = blockIdx.z;
    const int ig0 = blockIdx.x * 32;
    const int o0  = blockIdx.y * 32;
    const int IG = I * G;
    const int tx = threadIdx.x, ty = threadIdx.y;
    #pragma unroll
    for (int r = 0; r < 32; r += 8) {
        int o = o0 + ty + r;
        tile[ty + r][tx] = in[(size_t)(t * O + o) * IG + ig0 + tx];
    }
    __syncthreads();
    #pragma unroll
    for (int r = 0; r < 32; r += 8) {
        int ig = ig0 + ty + r;
        int i = ig / G, g = ig % G;
        int krow = i * 2 * G + t * G + g;
        out[(size_t)krow * O + o0 + tx] = to_tf32(tile[tx][ty + r]);
    }
}

// ---------------- K1: layer1 GEMM (fp32; small) ----------------
__global__ __launch_bounds__(256) void gemm1(const float* __restrict__ x,
                                             const float* __restrict__ W1,
                                             const float* __restrict__ b1,
                                             float* __restrict__ out) {
    __shared__ __align__(16) float As[16][68];
    __shared__ __align__(16) float Bs[16][68];
    const int tid = threadIdx.x;
    const int tx = tid & 15, ty = tid >> 4;
    const int n0 = blockIdx.x * 64, o0 = blockIdx.y * 64;
    float acc[4][4] = {};
    for (int k0 = 0; k0 < DIN; k0 += 16) {
        __syncthreads();
        #pragma unroll
        for (int lin = tid; lin < 1024; lin += 256) {
            int k = lin & 15, m = lin >> 4;
            As[k][m] = x[(n0 + m) * DIN + k0 + k];
            Bs[k][m] = W1[(o0 + m) * DIN + k0 + k];
        }
        __syncthreads();
        #pragma unroll
        for (int kk = 0; kk < 16; kk++) {
            float a[4], b[4];
            #pragma unroll
            for (int j = 0; j < 4; j++) { a[j] = As[kk][ty * 4 + j]; b[j] = Bs[kk][tx * 4 + j]; }
            #pragma unroll
            for (int im = 0; im < 4; im++)
                #pragma unroll
                for (int io = 0; io < 4; io++)
                    acc[im][io] += a[im] * b[io];
        }
    }
    #pragma unroll
    for (int im = 0; im < 4; im++) {
        int n = n0 + ty * 4 + im;
        #pragma unroll
        for (int io = 0; io < 4; io++) {
            int o = o0 + tx * 4 + io;
            out[n * H1DIM + o] = acc[im][io] + b1[o];
        }
    }
}

// ---------------- K2: deterministic BN stats ----------------
__global__ void reduce_stats() {
    __shared__ float ss[256], sq[256];
    const int tid = threadIdx.x;
    float s = 0.f, q = 0.f;
    for (int i = blockIdx.x * 256 + tid; i < BATCH * H1DIM; i += 256 * 256) {
        float v = g_Hpre[i];
        s += v; q += v * v;
    }
    ss[tid] = s; sq[tid] = q;
    __syncthreads();
    for (int off = 128; off; off >>= 1) {
        if (tid < off) { ss[tid] += ss[tid + off]; sq[tid] += sq[tid + off]; }
        __syncthreads();
    }
    if (tid == 0) { g_part[blockIdx.x] = ss[0]; g_part[256 + blockIdx.x] = sq[0]; }
}

__global__ void finalize_stats(const float* __restrict__ gamma, const float* __restrict__ beta) {
    __shared__ float ss[256], sq[256];
    const int tid = threadIdx.x;
    ss[tid] = g_part[tid]; sq[tid] = g_part[256 + tid];
    __syncthreads();
    for (int off = 128; off; off >>= 1) {
        if (tid < off) { ss[tid] += ss[tid + off]; sq[tid] += sq[tid + off]; }
        __syncthreads();
    }
    if (tid == 0) {
        const float inv_n = 1.0f / (float)(BATCH * H1DIM);
        float mean = ss[0] * inv_n;
        float var  = sq[0] * inv_n - mean * mean;
        float sc = gamma[0] * rsqrtf(var + BN_EPS);
        g_ss[0] = sc;
        g_ss[1] = beta[0] - mean * sc;
    }
}

// ---------------- K3: (optional BN+ReLU) -> cos/sin seed, transposed to [i][n] ----------------
__global__ void basis_seed(const float* __restrict__ src, float* __restrict__ Cd,
                           float* __restrict__ Sd, int useBN) {
    __shared__ float tc[32][33], tsn[32][33];
    const int i0 = blockIdx.x * 32, n0 = blockIdx.y * 32;
    const int tx = threadIdx.x, ty = threadIdx.y;
    float sc = 1.f, sh = 0.f;
    if (useBN) { sc = g_ss[0]; sh = g_ss[1]; }
    #pragma unroll
    for (int r = 0; r < 32; r += 8) {
        float v = src[(n0 + ty + r) * 512 + i0 + tx];
        v = sc * v + sh;
        if (useBN) v = fmaxf(v, 0.f);
        tc[ty + r][tx]  = cosf(v);
        tsn[ty + r][tx] = sinf(v);
    }
    __syncthreads();
    #pragma unroll
    for (int r = 0; r < 32; r += 8) {
        Cd[(i0 + ty + r) * BATCH + n0 + tx] = tc[tx][ty + r];
        Sd[(i0 + ty + r) * BATCH + n0 + tx] = tsn[tx][ty + r];
    }
}

// ---------------- K4/K5: Fourier-KAN GEMM via tf32 mma.sync (HMMA) ----------------
// CTA: 128(M) x 64(N), 8 warps of 32x32. K in chunks of 32 (F = 16/G features).
// Threads 0-127 generate harmonics (angle recurrence) -> smem A; threads 128-255
// load the pre-transposed tf32 coeff tile -> smem B. m16n8k8 tf32 MMAs.
template <int G, int NOUT>
__global__ __launch_bounds__(256) void kan_hmma(const float* __restrict__ Cseed,
                                                const float* __restrict__ Sseed,
                                                const float* __restrict__ Bmat,
                                                const float* __restrict__ bias,
                                                float* __restrict__ out) {
    constexpr int F = 16 / G;                // features per 32-wide K chunk (1 or 2)
    constexpr int NCHUNK = (512 * 2 * G) / 32;
    __shared__ float at[32][136];            // basis, pad 136 -> bank = 8k+n (conflict-free)
    __shared__ __align__(16) float bs[32][72]; // coeffs, pad 72 -> bank = 8k+n

    const int tid = threadIdx.x;
    const int wid = tid >> 5, lane = tid & 31;
    const int gid = lane >> 2, tig = lane & 3;
    const int wm = wid & 3, wn = wid >> 2;   // warp tile: rows wm*32, cols wn*32
    const int n0 = blockIdx.x * 128, o0 = blockIdx.y * 64;

    float acc[2][4][4];
    #pragma unroll
    for (int im = 0; im < 2; im++)
        #pragma unroll
        for (int in = 0; in < 4; in++)
            #pragma unroll
            for (int j = 0; j < 4; j++) acc[im][in][j] = 0.f;

    // seed state for basis-generating threads
    float curC[F], curS[F];
    if (tid < 128) {
        const int n = n0 + tid;
        #pragma unroll
        for (int f = 0; f < F; f++) {
            curC[f] = Cseed[(size_t)f * BATCH + n];
            curS[f] = Sseed[(size_t)f * BATCH + n];
        }
    }

    for (int t = 0; t < NCHUNK; t++) {
        __syncthreads();
        if (tid < 128) {
            // generate F features * 2G harmonics into at[][tid]
            #pragma unroll
            for (int f = 0; f < F; f++) {
                const float c1 = curC[f], s1 = curS[f];
                float c = c1, s = s1;
                #pragma unroll
                for (int g = 0; g < G; g++) {
                    at[f * 2 * G + g][tid]     = to_tf32(c);
                    at[f * 2 * G + G + g][tid] = to_tf32(s);
                    float cn = c * c1 - s * s1;
                    float sn = s * c1 + c * s1;
                    c = cn; s = sn;
                }
            }
            // prefetch next chunk's seeds
            if (t + 1 < NCHUNK) {
                const int n = n0 + tid;
                #pragma unroll
                for (int f = 0; f < F; f++) {
                    curC[f] = Cseed[(size_t)((t + 1) * F + f) * BATCH + n];
                    curS[f] = Sseed[(size_t)((t + 1) * F + f) * BATCH + n];
                }
            }
        } else {
            // load B tile: 32 rows x 64 cols, float4 per load, 4 loads/thread
            const int lt = tid - 128;
            const float* src = Bmat + (size_t)(t * 32) * NOUT + o0;
            #pragma unroll
            for (int j = 0; j < 4; j++) {
                int q = lt + j * 128;         // 0..511
                int k = q >> 4, o4 = (q & 15) << 2;
                *(float4*)&bs[k][o4] = *(const float4*)&src[(size_t)k * NOUT + o4];
            }
        }
        __syncthreads();
        // MMA: 4 k-steps of 8
        #pragma unroll
        for (int kk = 0; kk < 4; kk++) {
            uint32_t a[2][4], b[4][2];
            #pragma unroll
            for (int im = 0; im < 2; im++) {
                const int mrow = wm * 32 + im * 16;
                a[im][0] = __float_as_uint(at[kk * 8 + tig][mrow + gid]);
                a[im][1] = __float_as_uint(at[kk * 8 + tig][mrow + gid + 8]);
                a[im][2] = __float_as_uint(at[kk * 8 + tig + 4][mrow + gid]);
                a[im][3] = __float_as_uint(at[kk * 8 + tig + 4][mrow + gid + 8]);
            }
            #pragma unroll
            for (int in = 0; in < 4; in++) {
                const int ncol = wn * 32 + in * 8;
                b[in][0] = __float_as_uint(bs[kk * 8 + tig][ncol + gid]);
                b[in][1] = __float_as_uint(bs[kk * 8 + tig + 4][ncol + gid]);
            }
            #pragma unroll
            for (int im = 0; im < 2; im++)
                #pragma unroll
                for (int in = 0; in < 4; in++)
                    mma_tf32(acc[im][in][0], acc[im][in][1], acc[im][in][2], acc[im][in][3],
                             a[im][0], a[im][1], a[im][2], a[im][3], b[in][0], b[in][1]);
        }
    }

    // epilogue: C fragment -> global (+bias)
    #pragma unroll
    for (int im = 0; im < 2; im++) {
        const int r0 = n0 + wm * 32 + im * 16 + gid;
        #pragma unroll
        for (int in = 0; in < 4; in++) {
            const int col = o0 + wn * 32 + in * 8 + tig * 2;
            const float b0 = bias[col], b1 = bias[col + 1];
            float2 v0 = {acc[im][in][0] + b0, acc[im][in][1] + b1};
            float2 v1 = {acc[im][in][2] + b0, acc[im][in][3] + b1};
            *(float2*)&out[(size_t)r0 * NOUT + col] = v0;
            *(float2*)&out[(size_t)(r0 + 8) * NOUT + col] = v1;
        }
    }
}

// ---------------- K6: softmax over DOUT ----------------
__global__ void softmax_k(const float* __restrict__ in, float* __restrict__ out) {
    __shared__ float red[256];
    const int row = blockIdx.x, tid = threadIdx.x;
    float v = in[row * DOUT + tid];
    red[tid] = v;
    __syncthreads();
    for (int off = 128; off; off >>= 1) {
        if (tid < off) red[tid] = fmaxf(red[tid], red[tid + off]);
        __syncthreads();
    }
    float mx = red[0];
    __syncthreads();
    float e = expf(v - mx);
    red[tid] = e;
    __syncthreads();
    for (int off = 128; off; off >>= 1) {
        if (tid < off) red[tid] += red[tid + off];
        __syncthreads();
    }
    out[row * DOUT + tid] = e / red[0];
}

// ---------------- launch ----------------
extern "C" void kernel_launch(void* const* d_in, const int* in_sizes, int n_in,
                              void* d_out, int out_size) {
    const float* x       = (const float*)d_in[0];
    const float* W1      = (const float*)d_in[1];
    const float* b1      = (const float*)d_in[2];
    const float* gamma   = (const float*)d_in[3];
    const float* beta    = (const float*)d_in[4];
    const float* coeffs2 = (const float*)d_in[5];
    const float* bias2   = (const float*)d_in[6];
    const float* coeffs3 = (const float*)d_in[7];
    const float* bias3   = (const float*)d_in[8];
    float* out = (float*)d_out;

    float *pHpre, *pC1, *pS1, *pH2, *pC2, *pS2, *pB2, *pB3, *pH3;
    cudaGetSymbolAddress((void**)&pHpre, g_Hpre);
    cudaGetSymbolAddress((void**)&pC1, g_C1);
    cudaGetSymbolAddress((void**)&pS1, g_S1);
    cudaGetSymbolAddress((void**)&pH2, g_H2);
    cudaGetSymbolAddress((void**)&pC2, g_C2);
    cudaGetSymbolAddress((void**)&pS2, g_S2);
    cudaGetSymbolAddress((void**)&pB2, g_B2);
    cudaGetSymbolAddress((void**)&pB3, g_B3);
    cudaGetSymbolAddress((void**)&pH3, g_H3);

    // coeff layout transforms (tf32-rounded)
    transpose_coeffs<<<dim3((512 * G2) / 32, H2DIM / 32, 2), dim3(32, 8)>>>(coeffs2, pB2, H2DIM, H1DIM, G2);
    transpose_coeffs<<<dim3((512 * G3) / 32, DOUT / 32, 2), dim3(32, 8)>>>(coeffs3, pB3, DOUT, H2DIM, G3);

    // layer 1
    gemm1<<<dim3(BATCH / 64, H1DIM / 64), 256>>>(x, W1, b1, pHpre);

    // batchnorm stats (deterministic two-stage)
    reduce_stats<<<256, 256>>>();
    finalize_stats<<<1, 256>>>(gamma, beta);

    // layer 2: seeds (BN+ReLU fused) then HMMA KAN GEMM
    basis_seed<<<dim3(H1DIM / 32, BATCH / 32), dim3(32, 8)>>>(pHpre, pC1, pS1, 1);
    kan_hmma<G2, H2DIM><<<dim3(BATCH / 128, H2DIM / 64), 256>>>(pC1, pS1, pB2, bias2, pH2);

    // layer 3: seeds (identity) then HMMA KAN GEMM
    basis_seed<<<dim3(H2DIM / 32, BATCH / 32), dim3(32, 8)>>>(pH2, pC2, pS2, 0);
    kan_hmma<G3, DOUT><<<dim3(BATCH / 128, DOUT / 64), 256>>>(pC2, pS2, pB3, bias3, pH3);

    // softmax
    softmax_k<<<BATCH, 256>>>(pH3, out);
}

// round 9
// speedup vs baseline: 4.1744x; 1.6314x over previous
#include <cuda_runtime.h>
#include <cuda_fp16.h>
#include <math.h>
#include <stdint.h>

// Problem dims (fixed by reference setup_inputs)
#define BATCH 4096
#define DIN   256
#define H1DIM 512
#define H2DIM 512
#define DOUT  256
#define G2    16
#define G3    8
#define BN_EPS 1e-5f

// ---------------- scratch (static device allocations; no cudaMalloc) ----------------
__device__ float g_Hpre[BATCH * H1DIM];          // layer1 pre-BN output
__device__ float g_C1[H1DIM * BATCH];            // cos(a) seeds, [i][n]
__device__ float g_S1[H1DIM * BATCH];            // sin(a) seeds, [i][n]
__device__ float g_H2[BATCH * H2DIM];            // layer2 output
__device__ float g_C2[H2DIM * BATCH];            // layer3 seeds
__device__ float g_S2[H2DIM * BATCH];
__device__ __half g_B2[(size_t)H1DIM * 2 * G2 * H2DIM]; // coeffs2 [i*2G+t*G+g][o], fp16
__device__ __half g_B3[(size_t)H2DIM * 2 * G3 * DOUT];  // coeffs3 same layout
__device__ float g_H3[BATCH * DOUT];             // logits
__device__ float g_part[512];                    // partial sums (sum, sumsq)
__device__ float g_ss[2];                        // BN scale, shift

// ---------------- helpers ----------------
__device__ __forceinline__ uint32_t smem_u32(const void* p) {
    uint32_t a;
    asm("{ .reg .u64 t; cvta.to.shared.u64 t, %1; cvt.u32.u64 %0, t; }" : "=r"(a) : "l"(p));
    return a;
}
__device__ __forceinline__ void ldsm_x4_t(uint32_t& r0, uint32_t& r1, uint32_t& r2, uint32_t& r3,
                                          uint32_t addr) {
    asm volatile("ldmatrix.sync.aligned.m8n8.x4.trans.shared.b16 {%0,%1,%2,%3}, [%4];"
                 : "=r"(r0), "=r"(r1), "=r"(r2), "=r"(r3) : "r"(addr));
}
__device__ __forceinline__ void mma_fp16(float& c0, float& c1, float& c2, float& c3,
                                         uint32_t a0, uint32_t a1, uint32_t a2, uint32_t a3,
                                         uint32_t b0, uint32_t b1) {
    asm volatile(
        "mma.sync.aligned.m16n8k16.row.col.f32.f16.f16.f32 "
        "{%0,%1,%2,%3}, {%4,%5,%6,%7}, {%8,%9}, {%0,%1,%2,%3};"
        : "+f"(c0), "+f"(c1), "+f"(c2), "+f"(c3)
        : "r"(a0), "r"(a1), "r"(a2), "r"(a3), "r"(b0), "r"(b1));
}

// ---------------- K0: coeff layout transform (fp32 -> fp16) ----------------
// in:  [2][O][I][G] row-major   out: [(i*2G + t*G + g)][O]  fp16
__global__ void transpose_coeffs(const float* __restrict__ in, __half* __restrict__ out,
                                 int O, int I, int G) {
    __shared__ float tile[32][33];
    const int t  = blockIdx.z;
    const int ig0 = blockIdx.x * 32;
    const int o0  = blockIdx.y * 32;
    const int IG = I * G;
    const int tx = threadIdx.x, ty = threadIdx.y;
    #pragma unroll
    for (int r = 0; r < 32; r += 8) {
        int o = o0 + ty + r;
        tile[ty + r][tx] = in[(size_t)(t * O + o) * IG + ig0 + tx];
    }
    __syncthreads();
    #pragma unroll
    for (int r = 0; r < 32; r += 8) {
        int ig = ig0 + ty + r;
        int i = ig / G, g = ig % G;
        int krow = i * 2 * G + t * G + g;
        out[(size_t)krow * O + o0 + tx] = __float2half_rn(tile[tx][ty + r]);
    }
}

// ---------------- K1: layer1 GEMM (fp32; small) ----------------
__global__ __launch_bounds__(256) void gemm1(const float* __restrict__ x,
                                             const float* __restrict__ W1,
                                             const float* __restrict__ b1,
                                             float* __restrict__ out) {
    __shared__ __align__(16) float As[16][68];
    __shared__ __align__(16) float Bs[16][68];
    const int tid = threadIdx.x;
    const int tx = tid & 15, ty = tid >> 4;
    const int n0 = blockIdx.x * 64, o0 = blockIdx.y * 64;
    float acc[4][4] = {};
    for (int k0 = 0; k0 < DIN; k0 += 16) {
        __syncthreads();
        #pragma unroll
        for (int lin = tid; lin < 1024; lin += 256) {
            int k = lin & 15, m = lin >> 4;
            As[k][m] = x[(n0 + m) * DIN + k0 + k];
            Bs[k][m] = W1[(o0 + m) * DIN + k0 + k];
        }
        __syncthreads();
        #pragma unroll
        for (int kk = 0; kk < 16; kk++) {
            float a[4], b[4];
            #pragma unroll
            for (int j = 0; j < 4; j++) { a[j] = As[kk][ty * 4 + j]; b[j] = Bs[kk][tx * 4 + j]; }
            #pragma unroll
            for (int im = 0; im < 4; im++)
                #pragma unroll
                for (int io = 0; io < 4; io++)
                    acc[im][io] += a[im] * b[io];
        }
    }
    #pragma unroll
    for (int im = 0; im < 4; im++) {
        int n = n0 + ty * 4 + im;
        #pragma unroll
        for (int io = 0; io < 4; io++) {
            int o = o0 + tx * 4 + io;
            out[n * H1DIM + o] = acc[im][io] + b1[o];
        }
    }
}

// ---------------- K2: deterministic BN stats ----------------
__global__ void reduce_stats() {
    __shared__ float ss[256], sq[256];
    const int tid = threadIdx.x;
    float s = 0.f, q = 0.f;
    for (int i = blockIdx.x * 256 + tid; i < BATCH * H1DIM; i += 256 * 256) {
        float v = g_Hpre[i];
        s += v; q += v * v;
    }
    ss[tid] = s; sq[tid] = q;
    __syncthreads();
    for (int off = 128; off; off >>= 1) {
        if (tid < off) { ss[tid] += ss[tid + off]; sq[tid] += sq[tid + off]; }
        __syncthreads();
    }
    if (tid == 0) { g_part[blockIdx.x] = ss[0]; g_part[256 + blockIdx.x] = sq[0]; }
}

__global__ void finalize_stats(const float* __restrict__ gamma, const float* __restrict__ beta) {
    __shared__ float ss[256], sq[256];
    const int tid = threadIdx.x;
    ss[tid] = g_part[tid]; sq[tid] = g_part[256 + tid];
    __syncthreads();
    for (int off = 128; off; off >>= 1) {
        if (tid < off) { ss[tid] += ss[tid + off]; sq[tid] += sq[tid + off]; }
        __syncthreads();
    }
    if (tid == 0) {
        const float inv_n = 1.0f / (float)(BATCH * H1DIM);
        float mean = ss[0] * inv_n;
        float var  = sq[0] * inv_n - mean * mean;
        float sc = gamma[0] * rsqrtf(var + BN_EPS);
        g_ss[0] = sc;
        g_ss[1] = beta[0] - mean * sc;
    }
}

// ---------------- K3: (optional BN+ReLU) -> cos/sin seed, transposed to [i][n] ----------------
__global__ void basis_seed(const float* __restrict__ src, float* __restrict__ Cd,
                           float* __restrict__ Sd, int useBN) {
    __shared__ float tc[32][33], tsn[32][33];
    const int i0 = blockIdx.x * 32, n0 = blockIdx.y * 32;
    const int tx = threadIdx.x, ty = threadIdx.y;
    float sc = 1.f, sh = 0.f;
    if (useBN) { sc = g_ss[0]; sh = g_ss[1]; }
    #pragma unroll
    for (int r = 0; r < 32; r += 8) {
        float v = src[(n0 + ty + r) * 512 + i0 + tx];
        v = sc * v + sh;
        if (useBN) v = fmaxf(v, 0.f);
        tc[ty + r][tx]  = cosf(v);
        tsn[ty + r][tx] = sinf(v);
    }
    __syncthreads();
    #pragma unroll
    for (int r = 0; r < 32; r += 8) {
        Cd[(i0 + ty + r) * BATCH + n0 + tx] = tc[tx][ty + r];
        Sd[(i0 + ty + r) * BATCH + n0 + tx] = tsn[tx][ty + r];
    }
}

// ---------------- K4/K5: warp-specialized fp16 HMMA KAN GEMM ----------------
// CTA 256 thr: warps 0-3 produce (basis gen + B tile load, double-buffered smem),
// warps 4-7 consume (ldmatrix + m16n8k16 fp16 MMA). Tile 128(M) x 64(N); K chunk 32.
template <int G, int NOUT>
__global__ __launch_bounds__(256, 2) void kan_ws(const float* __restrict__ Cseed,
                                                 const float* __restrict__ Sseed,
                                                 const __half* __restrict__ Bmat,
                                                 const float* __restrict__ bias,
                                                 float* __restrict__ out) {
    constexpr int F = 16 / G;                // features per 32-wide chunk (1 or 2)
    constexpr int NCHUNK = 512 / F;          // 512 (G=16) or 256 (G=8)
    constexpr int AST = 136;                 // At row stride (halves): 272B = 17*16
    constexpr int BST = 72;                  // Bt row stride (halves): 144B = 9*16
    __shared__ __align__(256) __half At[2][32][AST];
    __shared__ __align__(256) __half Bt[2][32][BST];

    const int tid = threadIdx.x;
    const int wid = tid >> 5, lane = tid & 31;
    const int n0 = blockIdx.x * 128, o0 = blockIdx.y * 64;

    if (wid < 4) {
        // ================= PRODUCER (threads 0..127) =================
        const int m = tid;
        float curC[F], curS[F];

        // seeds for chunk 0
        #pragma unroll
        for (int f = 0; f < F; f++) {
            curC[f] = Cseed[(size_t)f * BATCH + n0 + m];
            curS[f] = Sseed[(size_t)f * BATCH + n0 + m];
        }
        // produce chunk 0 into buf 0
        {
            #pragma unroll
            for (int f = 0; f < F; f++) {
                const float c1 = curC[f], s1 = curS[f];
                float c = c1, s = s1;
                #pragma unroll
                for (int g = 0; g < G; g++) {
                    At[0][f * 2 * G + g][m]     = __float2half_rn(c);
                    At[0][f * 2 * G + G + g][m] = __float2half_rn(s);
                    float cn = c * c1 - s * s1;
                    float sn = s * c1 + c * s1;
                    c = cn; s = sn;
                }
            }
            // full B tile: 32 rows x 64 halves = 256 uint4; 2 per thread
            #pragma unroll
            for (int j = 0; j < 2; j++) {
                int q = tid + j * 128;
                int bk = q >> 3, bc = q & 7;
                *(uint4*)&Bt[0][bk][bc * 8] =
                    *(const uint4*)(Bmat + (size_t)bk * NOUT + o0 + bc * 8);
            }
            #pragma unroll
            for (int f = 0; f < F; f++) {   // seeds for chunk 1
                curC[f] = Cseed[(size_t)(F + f) * BATCH + n0 + m];
                curS[f] = Sseed[(size_t)(F + f) * BATCH + n0 + m];
            }
        }
        __syncthreads();
        for (int t = 0; t < NCHUNK; t++) {
            if (t + 1 < NCHUNK) {
                const int buf = (t + 1) & 1;
                #pragma unroll
                for (int f = 0; f < F; f++) {
                    const float c1 = curC[f], s1 = curS[f];
                    float c = c1, s = s1;
                    #pragma unroll
                    for (int g = 0; g < G; g++) {
                        At[buf][f * 2 * G + g][m]     = __float2half_rn(c);
                        At[buf][f * 2 * G + G + g][m] = __float2half_rn(s);
                        float cn = c * c1 - s * s1;
                        float sn = s * c1 + c * s1;
                        c = cn; s = sn;
                    }
                }
                #pragma unroll
                for (int j = 0; j < 2; j++) {
                    int q = tid + j * 128;
                    int bk = q >> 3, bc = q & 7;
                    *(uint4*)&Bt[buf][bk][bc * 8] =
                        *(const uint4*)(Bmat + (size_t)((t + 1) * 32 + bk) * NOUT + o0 + bc * 8);
                }
                if (t + 2 < NCHUNK) {
                    #pragma unroll
                    for (int f = 0; f < F; f++) {
                        curC[f] = Cseed[(size_t)((t + 2) * F + f) * BATCH + n0 + m];
                        curS[f] = Sseed[(size_t)((t + 2) * F + f) * BATCH + n0 + m];
                    }
                }
            }
            __syncthreads();
        }
    } else {
        // ================= CONSUMER (threads 128..255) =================
        const int cw = wid - 4;                 // 0..3, rows cw*32..cw*32+31
        const int m0 = cw * 32;
        const int gid = lane >> 2, tig = lane & 3;
        const int li = lane & 7, grp = lane >> 3;
        const uint32_t atB = smem_u32(&At[0][0][0]);
        const uint32_t btB = smem_u32(&Bt[0][0][0]);
        constexpr uint32_t ABUF = 32 * AST * 2; // bytes per A buffer
        constexpr uint32_t BBUF = 32 * BST * 2;

        // intra-buffer ldmatrix coords (lane-dependent, buf-independent)
        // A: row = ks + li + (grp>>1)*8, col = m0 + mt*16 + (grp&1)*8
        // B: row = ks + li + (grp&1)*8,  col = p*16 + (grp>>1)*8
        const uint32_t aRow = li + ((grp >> 1) << 3);
        const uint32_t aCol = m0 + ((grp & 1) << 3);
        const uint32_t bRow = li + ((grp & 1) << 3);
        const uint32_t bCol = ((grp >> 1) << 3);

        float acc[2][8][4];
        #pragma unroll
        for (int mt = 0; mt < 2; mt++)
            #pragma unroll
            for (int nt = 0; nt < 8; nt++)
                #pragma unroll
                for (int j = 0; j < 4; j++) acc[mt][nt][j] = 0.f;

        __syncthreads();
        for (int t = 0; t < NCHUNK; t++) {
            const uint32_t aBase = atB + (t & 1) * ABUF;
            const uint32_t bBase = btB + (t & 1) * BBUF;
            #pragma unroll
            for (int ks = 0; ks < 32; ks += 16) {
                uint32_t a[2][4], bb[4][4];
                #pragma unroll
                for (int mt = 0; mt < 2; mt++)
                    ldsm_x4_t(a[mt][0], a[mt][1], a[mt][2], a[mt][3],
                              aBase + ((ks + aRow) * AST + aCol + mt * 16) * 2);
                #pragma unroll
                for (int p = 0; p < 4; p++)
                    ldsm_x4_t(bb[p][0], bb[p][1], bb[p][2], bb[p][3],
                              bBase + ((ks + bRow) * BST + bCol + p * 16) * 2);
                #pragma unroll
                for (int mt = 0; mt < 2; mt++)
                    #pragma unroll
                    for (int nt = 0; nt < 8; nt++)
                        mma_fp16(acc[mt][nt][0], acc[mt][nt][1], acc[mt][nt][2], acc[mt][nt][3],
                                 a[mt][0], a[mt][1], a[mt][2], a[mt][3],
                                 bb[nt >> 1][(nt & 1) * 2], bb[nt >> 1][(nt & 1) * 2 + 1]);
            }
            __syncthreads();
        }
        // epilogue
        #pragma unroll
        for (int mt = 0; mt < 2; mt++) {
            const int r0 = n0 + m0 + mt * 16 + gid;
            #pragma unroll
            for (int nt = 0; nt < 8; nt++) {
                const int col = o0 + nt * 8 + tig * 2;
                const float b0 = bias[col], b1 = bias[col + 1];
                float2 v0 = {acc[mt][nt][0] + b0, acc[mt][nt][1] + b1};
                float2 v1 = {acc[mt][nt][2] + b0, acc[mt][nt][3] + b1};
                *(float2*)&out[(size_t)r0 * NOUT + col] = v0;
                *(float2*)&out[(size_t)(r0 + 8) * NOUT + col] = v1;
            }
        }
    }
}

// ---------------- K6: softmax over DOUT ----------------
__global__ void softmax_k(const float* __restrict__ in, float* __restrict__ out) {
    __shared__ float red[256];
    const int row = blockIdx.x, tid = threadIdx.x;
    float v = in[row * DOUT + tid];
    red[tid] = v;
    __syncthreads();
    for (int off = 128; off; off >>= 1) {
        if (tid < off) red[tid] = fmaxf(red[tid], red[tid + off]);
        __syncthreads();
    }
    float mx = red[0];
    __syncthreads();
    float e = expf(v - mx);
    red[tid] = e;
    __syncthreads();
    for (int off = 128; off; off >>= 1) {
        if (tid < off) red[tid] += red[tid + off];
        __syncthreads();
    }
    out[row * DOUT + tid] = e / red[0];
}

// ---------------- launch ----------------
extern "C" void kernel_launch(void* const* d_in, const int* in_sizes, int n_in,
                              void* d_out, int out_size) {
    const float* x       = (const float*)d_in[0];
    const float* W1      = (const float*)d_in[1];
    const float* b1      = (const float*)d_in[2];
    const float* gamma   = (const float*)d_in[3];
    const float* beta    = (const float*)d_in[4];
    const float* coeffs2 = (const float*)d_in[5];
    const float* bias2   = (const float*)d_in[6];
    const float* coeffs3 = (const float*)d_in[7];
    const float* bias3   = (const float*)d_in[8];
    float* out = (float*)d_out;

    float *pHpre, *pC1, *pS1, *pH2, *pC2, *pS2, *pH3;
    __half *pB2, *pB3;
    cudaGetSymbolAddress((void**)&pHpre, g_Hpre);
    cudaGetSymbolAddress((void**)&pC1, g_C1);
    cudaGetSymbolAddress((void**)&pS1, g_S1);
    cudaGetSymbolAddress((void**)&pH2, g_H2);
    cudaGetSymbolAddress((void**)&pC2, g_C2);
    cudaGetSymbolAddress((void**)&pS2, g_S2);
    cudaGetSymbolAddress((void**)&pB2, g_B2);
    cudaGetSymbolAddress((void**)&pB3, g_B3);
    cudaGetSymbolAddress((void**)&pH3, g_H3);

    // coeff layout transforms (fp32 -> fp16, [k][o])
    transpose_coeffs<<<dim3((512 * G2) / 32, H2DIM / 32, 2), dim3(32, 8)>>>(coeffs2, pB2, H2DIM, H1DIM, G2);
    transpose_coeffs<<<dim3((512 * G3) / 32, DOUT / 32, 2), dim3(32, 8)>>>(coeffs3, pB3, DOUT, H2DIM, G3);

    // layer 1
    gemm1<<<dim3(BATCH / 64, H1DIM / 64), 256>>>(x, W1, b1, pHpre);

    // batchnorm stats (deterministic two-stage)
    reduce_stats<<<256, 256>>>();
    finalize_stats<<<1, 256>>>(gamma, beta);

    // layer 2: seeds (BN+ReLU fused) then warp-specialized fp16 HMMA KAN GEMM
    basis_seed<<<dim3(H1DIM / 32, BATCH / 32), dim3(32, 8)>>>(pHpre, pC1, pS1, 1);
    kan_ws<G2, H2DIM><<<dim3(BATCH / 128, H2DIM / 64), 256>>>(pC1, pS1, pB2, bias2, pH2);

    // layer 3: seeds (identity) then warp-specialized fp16 HMMA KAN GEMM
    basis_seed<<<dim3(H2DIM / 32, BATCH / 32), dim3(32, 8)>>>(pH2, pC2, pS2, 0);
    kan_ws<G3, DOUT><<<dim3(BATCH / 128, DOUT / 64), 256>>>(pC2, pS2, pB3, bias3, pH3);

    // softmax
    softmax_k<<<BATCH, 256>>>(pH3, out);
}

// round 10
// speedup vs baseline: 5.7384x; 1.3747x over previous
#include <cuda_runtime.h>
#include <cuda_fp16.h>
#include <math.h>
#include <stdint.h>

// Problem dims (fixed by reference setup_inputs)
#define BATCH 4096
#define DIN   256
#define H1DIM 512
#define H2DIM 512
#define DOUT  256
#define G2    16
#define G3    8
#define BN_EPS 1e-5f

// ---------------- scratch (static device allocations; no cudaMalloc) ----------------
__device__ float g_Hpre[BATCH * H1DIM];          // layer1 pre-BN output
__device__ float g_C1[H1DIM * BATCH];            // cos(a) seeds, [i][n]
__device__ float g_S1[H1DIM * BATCH];            // sin(a) seeds, [i][n]
__device__ float g_H2[BATCH * H2DIM];            // layer2 output
__device__ float g_C2[H2DIM * BATCH];            // layer3 seeds
__device__ float g_S2[H2DIM * BATCH];
__device__ __half g_B2[(size_t)H1DIM * 2 * G2 * H2DIM]; // coeffs2 [i*2G+t*G+g][o], fp16
__device__ __half g_B3[(size_t)H2DIM * 2 * G3 * DOUT];  // coeffs3 same layout
__device__ float g_H3[BATCH * DOUT];             // logits
__device__ float g_part[512];                    // partial sums (sum, sumsq)
__device__ float g_ss[2];                        // BN scale, shift

// ---------------- helpers ----------------
__device__ __forceinline__ uint32_t smem_u32(const void* p) {
    uint32_t a;
    asm("{ .reg .u64 t; cvta.to.shared.u64 t, %1; cvt.u32.u64 %0, t; }" : "=r"(a) : "l"(p));
    return a;
}
__device__ __forceinline__ void ldsm_x4(uint32_t& r0, uint32_t& r1, uint32_t& r2, uint32_t& r3,
                                        uint32_t addr) {
    asm volatile("ldmatrix.sync.aligned.m8n8.x4.shared.b16 {%0,%1,%2,%3}, [%4];"
                 : "=r"(r0), "=r"(r1), "=r"(r2), "=r"(r3) : "r"(addr));
}
__device__ __forceinline__ void ldsm_x4_t(uint32_t& r0, uint32_t& r1, uint32_t& r2, uint32_t& r3,
                                          uint32_t addr) {
    asm volatile("ldmatrix.sync.aligned.m8n8.x4.trans.shared.b16 {%0,%1,%2,%3}, [%4];"
                 : "=r"(r0), "=r"(r1), "=r"(r2), "=r"(r3) : "r"(addr));
}
__device__ __forceinline__ void mma_fp16(float& c0, float& c1, float& c2, float& c3,
                                         uint32_t a0, uint32_t a1, uint32_t a2, uint32_t a3,
                                         uint32_t b0, uint32_t b1) {
    asm volatile(
        "mma.sync.aligned.m16n8k16.row.col.f32.f16.f16.f32 "
        "{%0,%1,%2,%3}, {%4,%5,%6,%7}, {%8,%9}, {%0,%1,%2,%3};"
        : "+f"(c0), "+f"(c1), "+f"(c2), "+f"(c3)
        : "r"(a0), "r"(a1), "r"(a2), "r"(a3), "r"(b0), "r"(b1));
}
__device__ __forceinline__ uint32_t f2_to_u32(float a, float b) {
    __half2 h = __floats2half2_rn(a, b);   // a -> low half (lower k index)
    uint32_t u;
    memcpy(&u, &h, 4);
    return u;
}

// ---------------- K0: coeff layout transform (fp32 -> fp16) ----------------
// in:  [2][O][I][G] row-major   out: [(i*2G + t*G + g)][O]  fp16
__global__ void transpose_coeffs(const float* __restrict__ in, __half* __restrict__ out,
                                 int O, int I, int G) {
    __shared__ float tile[32][33];
    const int t  = blockIdx.z;
    const int ig0 = blockIdx.x * 32;
    const int o0  = blockIdx.y * 32;
    const int IG = I * G;
    const int tx = threadIdx.x, ty = threadIdx.y;
    #pragma unroll
    for (int r = 0; r < 32; r += 8) {
        int o = o0 + ty + r;
        tile[ty + r][tx] = in[(size_t)(t * O + o) * IG + ig0 + tx];
    }
    __syncthreads();
    #pragma unroll
    for (int r = 0; r < 32; r += 8) {
        int ig = ig0 + ty + r;
        int i = ig / G, g = ig % G;
        int krow = i * 2 * G + t * G + g;
        out[(size_t)krow * O + o0 + tx] = __float2half_rn(tile[tx][ty + r]);
    }
}

// ---------------- K1: layer1 GEMM (fp32; small) ----------------
__global__ __launch_bounds__(256) void gemm1(const float* __restrict__ x,
                                             const float* __restrict__ W1,
                                             const float* __restrict__ b1,
                                             float* __restrict__ out) {
    __shared__ __align__(16) float As[16][68];
    __shared__ __align__(16) float Bs[16][68];
    const int tid = threadIdx.x;
    const int tx = tid & 15, ty = tid >> 4;
    const int n0 = blockIdx.x * 64, o0 = blockIdx.y * 64;
    float acc[4][4] = {};
    for (int k0 = 0; k0 < DIN; k0 += 16) {
        __syncthreads();
        #pragma unroll
        for (int lin = tid; lin < 1024; lin += 256) {
            int k = lin & 15, m = lin >> 4;
            As[k][m] = x[(n0 + m) * DIN + k0 + k];
            Bs[k][m] = W1[(o0 + m) * DIN + k0 + k];
        }
        __syncthreads();
        #pragma unroll
        for (int kk = 0; kk < 16; kk++) {
            float a[4], b[4];
            #pragma unroll
            for (int j = 0; j < 4; j++) { a[j] = As[kk][ty * 4 + j]; b[j] = Bs[kk][tx * 4 + j]; }
            #pragma unroll
            for (int im = 0; im < 4; im++)
                #pragma unroll
                for (int io = 0; io < 4; io++)
                    acc[im][io] += a[im] * b[io];
        }
    }
    #pragma unroll
    for (int im = 0; im < 4; im++) {
        int n = n0 + ty * 4 + im;
        #pragma unroll
        for (int io = 0; io < 4; io++) {
            int o = o0 + tx * 4 + io;
            out[n * H1DIM + o] = acc[im][io] + b1[o];
        }
    }
}

// ---------------- K2: deterministic BN stats ----------------
__global__ void reduce_stats() {
    __shared__ float ss[256], sq[256];
    const int tid = threadIdx.x;
    float s = 0.f, q = 0.f;
    for (int i = blockIdx.x * 256 + tid; i < BATCH * H1DIM; i += 256 * 256) {
        float v = g_Hpre[i];
        s += v; q += v * v;
    }
    ss[tid] = s; sq[tid] = q;
    __syncthreads();
    for (int off = 128; off; off >>= 1) {
        if (tid < off) { ss[tid] += ss[tid + off]; sq[tid] += sq[tid + off]; }
        __syncthreads();
    }
    if (tid == 0) { g_part[blockIdx.x] = ss[0]; g_part[256 + blockIdx.x] = sq[0]; }
}

__global__ void finalize_stats(const float* __restrict__ gamma, const float* __restrict__ beta) {
    __shared__ float ss[256], sq[256];
    const int tid = threadIdx.x;
    ss[tid] = g_part[tid]; sq[tid] = g_part[256 + tid];
    __syncthreads();
    for (int off = 128; off; off >>= 1) {
        if (tid < off) { ss[tid] += ss[tid + off]; sq[tid] += sq[tid + off]; }
        __syncthreads();
    }
    if (tid == 0) {
        const float inv_n = 1.0f / (float)(BATCH * H1DIM);
        float mean = ss[0] * inv_n;
        float var  = sq[0] * inv_n - mean * mean;
        float sc = gamma[0] * rsqrtf(var + BN_EPS);
        g_ss[0] = sc;
        g_ss[1] = beta[0] - mean * sc;
    }
}

// ---------------- K3: (optional BN+ReLU) -> cos/sin seed, transposed to [i][n] ----------------
__global__ void basis_seed(const float* __restrict__ src, float* __restrict__ Cd,
                           float* __restrict__ Sd, int useBN) {
    __shared__ float tc[32][33], tsn[32][33];
    const int i0 = blockIdx.x * 32, n0 = blockIdx.y * 32;
    const int tx = threadIdx.x, ty = threadIdx.y;
    float sc = 1.f, sh = 0.f;
    if (useBN) { sc = g_ss[0]; sh = g_ss[1]; }
    #pragma unroll
    for (int r = 0; r < 32; r += 8) {
        float v = src[(n0 + ty + r) * 512 + i0 + tx];
        v = sc * v + sh;
        if (useBN) v = fmaxf(v, 0.f);
        tc[ty + r][tx]  = cosf(v);
        tsn[ty + r][tx] = sinf(v);
    }
    __syncthreads();
    #pragma unroll
    for (int r = 0; r < 32; r += 8) {
        Cd[(i0 + ty + r) * BATCH + n0 + tx] = tc[tx][ty + r];
        Sd[(i0 + ty + r) * BATCH + n0 + tx] = tsn[tx][ty + r];
    }
}

// ---------------- K4/K5: warp-specialized fp16 HMMA KAN GEMM, K-chunk 64 ----------------
// CTA 256 thr: warps 0-3 produce (basis -> m-major A tile via STS.128 + B tile),
// warps 4-7 consume (ldmatrix + m16n8k16). Tile 128(M) x 64(N); K chunk 64.
// At: [buf][m(128)][AST=72] halves (m-major, non-trans LDSM for A).
// Bt: [buf][k(64)][BST=72] halves (k-major, trans LDSM for B).
#define AST 72
#define BST 72
#define KCH 64
template <int G, int NOUT>
__global__ __launch_bounds__(256, 2) void kan_ws(const float* __restrict__ Cseed,
                                                 const float* __restrict__ Sseed,
                                                 const __half* __restrict__ Bmat,
                                                 const float* __restrict__ bias,
                                                 float* __restrict__ out) {
    constexpr int F = KCH / (2 * G);         // features per chunk: 2 (G=16) or 4 (G=8)
    constexpr int NCHUNK = 512 / F;          // 256 or 128
    constexpr int ABUF_H = 128 * AST;        // halves per A buffer
    constexpr int BBUF_H = KCH * BST;
    extern __shared__ __half dsm[];
    __half* AtB = dsm;                       // 2 buffers
    __half* BtB = dsm + 2 * ABUF_H;

    const int tid = threadIdx.x;
    const int wid = tid >> 5, lane = tid & 31;
    const int n0 = blockIdx.x * 128, o0 = blockIdx.y * 64;

    if (wid < 4) {
        // ================= PRODUCER (threads 0..127) =================
        const int m = tid;
        float curC[F], curS[F];
        #pragma unroll
        for (int f = 0; f < F; f++) {
            curC[f] = Cseed[(size_t)f * BATCH + n0 + m];
            curS[f] = Sseed[(size_t)f * BATCH + n0 + m];
        }
        // produce chunk 0 into buf 0, then steady-state
        for (int t = -1; t < NCHUNK; t++) {
            const int pc = t + 1;            // chunk being produced
            if (pc < NCHUNK) {
                const int buf = pc & 1;
                __half* rowp = AtB + buf * ABUF_H + m * AST;
                #pragma unroll
                for (int f = 0; f < F; f++) {
                    const float c1 = curC[f], s1 = curS[f];
                    float c = c1, s = s1, pcv = 0.f, psv = 0.f;
                    uint32_t hc[G / 2], hs[G / 2];
                    #pragma unroll
                    for (int g = 0; g < G; g++) {
                        if ((g & 1) == 0) { pcv = c; psv = s; }
                        else { hc[g >> 1] = f2_to_u32(pcv, c); hs[g >> 1] = f2_to_u32(psv, s); }
                        float cn = c * c1 - s * s1;
                        float sn = s * c1 + c * s1;
                        c = cn; s = sn;
                    }
                    // cos at k = f*2G .. +G-1, sin at f*2G+G .. +2G-1
                    #pragma unroll
                    for (int j = 0; j < G / 8; j++) {
                        *(uint4*)(rowp + f * 2 * G + j * 8) =
                            make_uint4(hc[4 * j], hc[4 * j + 1], hc[4 * j + 2], hc[4 * j + 3]);
                        *(uint4*)(rowp + f * 2 * G + G + j * 8) =
                            make_uint4(hs[4 * j], hs[4 * j + 1], hs[4 * j + 2], hs[4 * j + 3]);
                    }
                }
                // B tile: 64 rows x 64 halves = 512 uint4; 4 per thread
                __half* bdst = BtB + buf * BBUF_H;
                #pragma unroll
                for (int j = 0; j < 4; j++) {
                    int q = tid + j * 128;
                    int bk = q >> 3, bc = q & 7;
                    *(uint4*)(bdst + bk * BST + bc * 8) =
                        *(const uint4*)(Bmat + (size_t)(pc * KCH + bk) * NOUT + o0 + bc * 8);
                }
                // prefetch seeds for chunk pc+1
                if (pc + 1 < NCHUNK) {
                    #pragma unroll
                    for (int f = 0; f < F; f++) {
                        curC[f] = Cseed[(size_t)((pc + 1) * F + f) * BATCH + n0 + m];
                        curS[f] = Sseed[(size_t)((pc + 1) * F + f) * BATCH + n0 + m];
                    }
                }
            }
            __syncthreads();
        }
    } else {
        // ================= CONSUMER (threads 128..255) =================
        const int cw = wid - 4;                 // rows cw*32 .. cw*32+31
        const int m0 = cw * 32;
        const int gid = lane >> 2, tig = lane & 3;
        const int li = lane & 7, grp = lane >> 3;
        const uint32_t atB = smem_u32(AtB);
        const uint32_t btB = smem_u32(BtB);
        constexpr uint32_t ABUF_B = ABUF_H * 2;
        constexpr uint32_t BBUF_B = BBUF_H * 2;

        // A (non-trans, 16x16 row-major): lanes 0-15 -> row m0+mt*16+(lane&15), col ks
        //                                 lanes 16-31 -> same rows, col ks+8
        const uint32_t aRowL = lane & 15;
        const uint32_t aColS = (lane >> 4) << 3;
        // B (trans, k-major): row = ks + li + (grp&1)*8, col = p*16 + (grp>>1)*8
        const uint32_t bRow = li + ((grp & 1) << 3);
        const uint32_t bCol = ((grp >> 1) << 3);

        float acc[2][8][4];
        #pragma unroll
        for (int mt = 0; mt < 2; mt++)
            #pragma unroll
            for (int nt = 0; nt < 8; nt++)
                #pragma unroll
                for (int j = 0; j < 4; j++) acc[mt][nt][j] = 0.f;

        __syncthreads();
        for (int t = 0; t < NCHUNK; t++) {
            const uint32_t aBase = atB + (t & 1) * ABUF_B;
            const uint32_t bBase = btB + (t & 1) * BBUF_B;
            #pragma unroll
            for (int ks = 0; ks < KCH; ks += 16) {
                uint32_t a[2][4], bb[4][4];
                #pragma unroll
                for (int mt = 0; mt < 2; mt++)
                    ldsm_x4(a[mt][0], a[mt][1], a[mt][2], a[mt][3],
                            aBase + ((m0 + mt * 16 + aRowL) * AST + ks + aColS) * 2);
                #pragma unroll
                for (int p = 0; p < 4; p++)
                    ldsm_x4_t(bb[p][0], bb[p][1], bb[p][2], bb[p][3],
                              bBase + ((ks + bRow) * BST + bCol + p * 16) * 2);
                #pragma unroll
                for (int mt = 0; mt < 2; mt++)
                    #pragma unroll
                    for (int nt = 0; nt < 8; nt++)
                        mma_fp16(acc[mt][nt][0], acc[mt][nt][1], acc[mt][nt][2], acc[mt][nt][3],
                                 a[mt][0], a[mt][1], a[mt][2], a[mt][3],
                                 bb[nt >> 1][(nt & 1) * 2], bb[nt >> 1][(nt & 1) * 2 + 1]);
            }
            __syncthreads();
        }
        // epilogue
        #pragma unroll
        for (int mt = 0; mt < 2; mt++) {
            const int r0 = n0 + m0 + mt * 16 + gid;
            #pragma unroll
            for (int nt = 0; nt < 8; nt++) {
                const int col = o0 + nt * 8 + tig * 2;
                const float b0 = bias[col], b1 = bias[col + 1];
                float2 v0 = {acc[mt][nt][0] + b0, acc[mt][nt][1] + b1};
                float2 v1 = {acc[mt][nt][2] + b0, acc[mt][nt][3] + b1};
                *(float2*)&out[(size_t)r0 * NOUT + col] = v0;
                *(float2*)&out[(size_t)(r0 + 8) * NOUT + col] = v1;
            }
        }
    }
}

// ---------------- K6: softmax over DOUT ----------------
__global__ void softmax_k(const float* __restrict__ in, float* __restrict__ out) {
    __shared__ float red[256];
    const int row = blockIdx.x, tid = threadIdx.x;
    float v = in[row * DOUT + tid];
    red[tid] = v;
    __syncthreads();
    for (int off = 128; off; off >>= 1) {
        if (tid < off) red[tid] = fmaxf(red[tid], red[tid + off]);
        __syncthreads();
    }
    float mx = red[0];
    __syncthreads();
    float e = expf(v - mx);
    red[tid] = e;
    __syncthreads();
    for (int off = 128; off; off >>= 1) {
        if (tid < off) red[tid] += red[tid + off];
        __syncthreads();
    }
    out[row * DOUT + tid] = e / red[0];
}

// ---------------- launch ----------------
extern "C" void kernel_launch(void* const* d_in, const int* in_sizes, int n_in,
                              void* d_out, int out_size) {
    const float* x       = (const float*)d_in[0];
    const float* W1      = (const float*)d_in[1];
    const float* b1      = (const float*)d_in[2];
    const float* gamma   = (const float*)d_in[3];
    const float* beta    = (const float*)d_in[4];
    const float* coeffs2 = (const float*)d_in[5];
    const float* bias2   = (const float*)d_in[6];
    const float* coeffs3 = (const float*)d_in[7];
    const float* bias3   = (const float*)d_in[8];
    float* out = (float*)d_out;

    float *pHpre, *pC1, *pS1, *pH2, *pC2, *pS2, *pH3;
    __half *pB2, *pB3;
    cudaGetSymbolAddress((void**)&pHpre, g_Hpre);
    cudaGetSymbolAddress((void**)&pC1, g_C1);
    cudaGetSymbolAddress((void**)&pS1, g_S1);
    cudaGetSymbolAddress((void**)&pH2, g_H2);
    cudaGetSymbolAddress((void**)&pC2, g_C2);
    cudaGetSymbolAddress((void**)&pS2, g_S2);
    cudaGetSymbolAddress((void**)&pB2, g_B2);
    cudaGetSymbolAddress((void**)&pB3, g_B3);
    cudaGetSymbolAddress((void**)&pH3, g_H3);

    const int smem_bytes = (2 * 128 * AST + 2 * KCH * BST) * 2;   // 55296
    cudaFuncSetAttribute(kan_ws<G2, H2DIM>, cudaFuncAttributeMaxDynamicSharedMemorySize, smem_bytes);
    cudaFuncSetAttribute(kan_ws<G3, DOUT>,  cudaFuncAttributeMaxDynamicSharedMemorySize, smem_bytes);

    // coeff layout transforms (fp32 -> fp16, [k][o])
    transpose_coeffs<<<dim3((512 * G2) / 32, H2DIM / 32, 2), dim3(32, 8)>>>(coeffs2, pB2, H2DIM, H1DIM, G2);
    transpose_coeffs<<<dim3((512 * G3) / 32, DOUT / 32, 2), dim3(32, 8)>>>(coeffs3, pB3, DOUT, H2DIM, G3);

    // layer 1
    gemm1<<<dim3(BATCH / 64, H1DIM / 64), 256>>>(x, W1, b1, pHpre);

    // batchnorm stats (deterministic two-stage)
    reduce_stats<<<256, 256>>>();
    finalize_stats<<<1, 256>>>(gamma, beta);

    // layer 2: seeds (BN+ReLU fused) then warp-specialized fp16 HMMA KAN GEMM
    basis_seed<<<dim3(H1DIM / 32, BATCH / 32), dim3(32, 8)>>>(pHpre, pC1, pS1, 1);
    kan_ws<G2, H2DIM><<<dim3(BATCH / 128, H2DIM / 64), 256, smem_bytes>>>(pC1, pS1, pB2, bias2, pH2);

    // layer 3: seeds (identity) then warp-specialized fp16 HMMA KAN GEMM
    basis_seed<<<dim3(H2DIM / 32, BATCH / 32), dim3(32, 8)>>>(pH2, pC2, pS2, 0);
    kan_ws<G3, DOUT><<<dim3(BATCH / 128, DOUT / 64), 256, smem_bytes>>>(pC2, pS2, pB3, bias3, pH3);

    // softmax
    softmax_k<<<BATCH, 256>>>(pH3, out);
}

// round 13
// speedup vs baseline: 6.1431x; 1.0705x over previous
#include <cuda_runtime.h>
#include <cuda_fp16.h>
#include <math.h>
#include <stdint.h>

// Problem dims (fixed by reference setup_inputs)
#define BATCH 4096
#define DIN   256
#define H1DIM 512
#define H2DIM 512
#define DOUT  256
#define G2    16
#define G3    8
#define BN_EPS 1e-5f

// ---------------- scratch (static device allocations; no cudaMalloc) ----------------
__device__ float g_Hpre[BATCH * H1DIM];          // layer1 pre-BN output
__device__ float g_C1[H1DIM * BATCH];            // cos(a) seeds, [i][n]
__device__ float g_S1[H1DIM * BATCH];            // sin(a) seeds, [i][n]
__device__ float g_H2[BATCH * H2DIM];            // layer2 output
__device__ float g_C2[H2DIM * BATCH];            // layer3 seeds
__device__ float g_S2[H2DIM * BATCH];
__device__ __half g_B2[(size_t)H1DIM * 2 * G2 * H2DIM]; // coeffs2 [i*2G+t*G+g][o], fp16
__device__ __half g_B3[(size_t)H2DIM * 2 * G3 * DOUT];  // coeffs3 same layout
__device__ float g_H3[BATCH * DOUT];             // logits
__device__ float g_part[512];                    // partial sums (sum, sumsq)
__device__ float g_ss[2];                        // BN scale, shift

// ---------------- helpers ----------------
__device__ __forceinline__ uint32_t smem_u32(const void* p) {
    uint32_t a;
    asm("{ .reg .u64 t; cvta.to.shared.u64 t, %1; cvt.u32.u64 %0, t; }" : "=r"(a) : "l"(p));
    return a;
}
__device__ __forceinline__ void ldsm_x4(uint32_t& r0, uint32_t& r1, uint32_t& r2, uint32_t& r3,
                                        uint32_t addr) {
    asm volatile("ldmatrix.sync.aligned.m8n8.x4.shared.b16 {%0,%1,%2,%3}, [%4];"
                 : "=r"(r0), "=r"(r1), "=r"(r2), "=r"(r3) : "r"(addr));
}
__device__ __forceinline__ void ldsm_x4_t(uint32_t& r0, uint32_t& r1, uint32_t& r2, uint32_t& r3,
                                          uint32_t addr) {
    asm volatile("ldmatrix.sync.aligned.m8n8.x4.trans.shared.b16 {%0,%1,%2,%3}, [%4];"
                 : "=r"(r0), "=r"(r1), "=r"(r2), "=r"(r3) : "r"(addr));
}
__device__ __forceinline__ void mma_fp16(float& c0, float& c1, float& c2, float& c3,
                                         uint32_t a0, uint32_t a1, uint32_t a2, uint32_t a3,
                                         uint32_t b0, uint32_t b1) {
    asm volatile(
        "mma.sync.aligned.m16n8k16.row.col.f32.f16.f16.f32 "
        "{%0,%1,%2,%3}, {%4,%5,%6,%7}, {%8,%9}, {%0,%1,%2,%3};"
        : "+f"(c0), "+f"(c1), "+f"(c2), "+f"(c3)
        : "r"(a0), "r"(a1), "r"(a2), "r"(a3), "r"(b0), "r"(b1));
}
__device__ __forceinline__ uint32_t f2_to_u32(float a, float b) {
    __half2 h = __floats2half2_rn(a, b);   // a -> low half (lower k index)
    uint32_t u;
    memcpy(&u, &h, 4);
    return u;
}
// split producer/consumer named barriers (count = 128 arrivers + 128 waiters)
#define BAR_WAIT(id)   asm volatile("bar.sync %0, 256;"   :: "r"(id) : "memory")
#define BAR_ARRIVE(id) asm volatile("bar.arrive %0, 256;" :: "r"(id) : "memory")
#define FULL_BAR(buf)  (1 + (buf))
#define EMPTY_BAR(buf) (3 + (buf))

// ---------------- coeff layout transform (fp32 -> fp16) ----------------
// in:  [2][O][I][G] row-major   out: [(i*2G + t*G + g)][O]  fp16
__global__ void transpose_coeffs(const float* __restrict__ in, __half* __restrict__ out,
                                 int O, int I, int G) {
    __shared__ float tile[32][33];
    const int t  = blockIdx.z;
    const int ig0 = blockIdx.x * 32;
    const int o0  = blockIdx.y * 32;
    const int IG = I * G;
    const int tx = threadIdx.x, ty = threadIdx.y;
    #pragma unroll
    for (int r = 0; r < 32; r += 8) {
        int o = o0 + ty + r;
        tile[ty + r][tx] = in[(size_t)(t * O + o) * IG + ig0 + tx];
    }
    __syncthreads();
    #pragma unroll
    for (int r = 0; r < 32; r += 8) {
        int ig = ig0 + ty + r;
        int i = ig / G, g = ig % G;
        int krow = i * 2 * G + t * G + g;
        out[(size_t)krow * O + o0 + tx] = __float2half_rn(tile[tx][ty + r]);
    }
}

// ---------------- layer1 GEMM (fp32; small) ----------------
__global__ __launch_bounds__(256) void gemm1(const float* __restrict__ x,
                                             const float* __restrict__ W1,
                                             const float* __restrict__ b1,
                                             float* __restrict__ out) {
    __shared__ __align__(16) float As[16][68];
    __shared__ __align__(16) float Bs[16][68];
    const int tid = threadIdx.x;
    const int tx = tid & 15, ty = tid >> 4;
    const int n0 = blockIdx.x * 64, o0 = blockIdx.y * 64;
    float acc[4][4] = {};
    for (int k0 = 0; k0 < DIN; k0 += 16) {
        __syncthreads();
        #pragma unroll
        for (int lin = tid; lin < 1024; lin += 256) {
            int k = lin & 15, m = lin >> 4;
            As[k][m] = x[(n0 + m) * DIN + k0 + k];
            Bs[k][m] = W1[(o0 + m) * DIN + k0 + k];
        }
        __syncthreads();
        #pragma unroll
        for (int kk = 0; kk < 16; kk++) {
            float a[4], b[4];
            #pragma unroll
            for (int j = 0; j < 4; j++) { a[j] = As[kk][ty * 4 + j]; b[j] = Bs[kk][tx * 4 + j]; }
            #pragma unroll
            for (int im = 0; im < 4; im++)
                #pragma unroll
                for (int io = 0; io < 4; io++)
                    acc[im][io] += a[im] * b[io];
        }
    }
    #pragma unroll
    for (int im = 0; im < 4; im++) {
        int n = n0 + ty * 4 + im;
        #pragma unroll
        for (int io = 0; io < 4; io++) {
            int o = o0 + tx * 4 + io;
            out[n * H1DIM + o] = acc[im][io] + b1[o];
        }
    }
}

// ---------------- deterministic BN stats ----------------
__global__ void reduce_stats() {
    __shared__ float ss[256], sq[256];
    const int tid = threadIdx.x;
    float s = 0.f, q = 0.f;
    for (int i = blockIdx.x * 256 + tid; i < BATCH * H1DIM; i += 256 * 256) {
        float v = g_Hpre[i];
        s += v; q += v * v;
    }
    ss[tid] = s; sq[tid] = q;
    __syncthreads();
    for (int off = 128; off; off >>= 1) {
        if (tid < off) { ss[tid] += ss[tid + off]; sq[tid] += sq[tid + off]; }
        __syncthreads();
    }
    if (tid == 0) { g_part[blockIdx.x] = ss[0]; g_part[256 + blockIdx.x] = sq[0]; }
}

__global__ void finalize_stats(const float* __restrict__ gamma, const float* __restrict__ beta) {
    __shared__ float ss[256], sq[256];
    const int tid = threadIdx.x;
    ss[tid] = g_part[tid]; sq[tid] = g_part[256 + tid];
    __syncthreads();
    for (int off = 128; off; off >>= 1) {
        if (tid < off) { ss[tid] += ss[tid + off]; sq[tid] += sq[tid + off]; }
        __syncthreads();
    }
    if (tid == 0) {
        const float inv_n = 1.0f / (float)(BATCH * H1DIM);
        float mean = ss[0] * inv_n;
        float var  = sq[0] * inv_n - mean * mean;
        float sc = gamma[0] * rsqrtf(var + BN_EPS);
        g_ss[0] = sc;
        g_ss[1] = beta[0] - mean * sc;
    }
}

// ---------------- (optional BN+ReLU) -> cos/sin seed, transposed to [i][n] ----------------
__global__ void basis_seed(const float* __restrict__ src, float* __restrict__ Cd,
                           float* __restrict__ Sd, int useBN) {
    __shared__ float tc[32][33], tsn[32][33];
    const int i0 = blockIdx.x * 32, n0 = blockIdx.y * 32;
    const int tx = threadIdx.x, ty = threadIdx.y;
    float sc = 1.f, sh = 0.f;
    if (useBN) { sc = g_ss[0]; sh = g_ss[1]; }
    #pragma unroll
    for (int r = 0; r < 32; r += 8) {
        float v = src[(n0 + ty + r) * 512 + i0 + tx];
        v = sc * v + sh;
        if (useBN) v = fmaxf(v, 0.f);
        tc[ty + r][tx]  = cosf(v);
        tsn[ty + r][tx] = sinf(v);
    }
    __syncthreads();
    #pragma unroll
    for (int r = 0; r < 32; r += 8) {
        Cd[(i0 + ty + r) * BATCH + n0 + tx] = tc[tx][ty + r];
        Sd[(i0 + ty + r) * BATCH + n0 + tx] = tsn[tx][ty + r];
    }
}

// ---------------- warp-specialized fp16 HMMA KAN GEMM, split named barriers ----------------
// CTA 256 thr: warps 0-3 produce (basis -> m-major A tile via STS.128 + B tile),
// warps 4-7 consume (ldmatrix + m16n8k16). Tile 128(M) x 64(N); K chunk 64.
// Producer runs up to one buffer ahead via FULL/EMPTY named barriers.
#define AST 72
#define BST 72
#define KCH 64
template <int G, int NOUT>
__global__ __launch_bounds__(256, 2) void kan_ws(const float* __restrict__ Cseed,
                                                 const float* __restrict__ Sseed,
                                                 const __half* __restrict__ Bmat,
                                                 const float* __restrict__ bias,
                                                 float* __restrict__ out) {
    constexpr int F = KCH / (2 * G);         // features per chunk: 2 (G=16) or 4 (G=8)
    constexpr int NCHUNK = 512 / F;          // 256 or 128
    constexpr int ABUF_H = 128 * AST;        // halves per A buffer
    constexpr int BBUF_H = KCH * BST;
    extern __shared__ __half dsm[];
    __half* AtB = dsm;                       // 2 buffers
    __half* BtB = dsm + 2 * ABUF_H;

    const int tid = threadIdx.x;
    const int wid = tid >> 5, lane = tid & 31;
    const int n0 = blockIdx.x * 128, o0 = blockIdx.y * 64;

    if (wid < 4) {
        // ================= PRODUCER (threads 0..127) =================
        const int m = tid;
        float curC[F], curS[F];
        #pragma unroll
        for (int f = 0; f < F; f++) {
            curC[f] = Cseed[(size_t)f * BATCH + n0 + m];
            curS[f] = Sseed[(size_t)f * BATCH + n0 + m];
        }
        for (int pc = 0; pc < NCHUNK; pc++) {
            const int buf = pc & 1;
            if (pc >= 2) BAR_WAIT(EMPTY_BAR(buf));
            __half* rowp = AtB + buf * ABUF_H + m * AST;
            #pragma unroll
            for (int f = 0; f < F; f++) {
                const float c1 = curC[f], s1 = curS[f];
                float c = c1, s = s1, pcv = 0.f, psv = 0.f;
                uint32_t hc[G / 2], hs[G / 2];
                #pragma unroll
                for (int g = 0; g < G; g++) {
                    if ((g & 1) == 0) { pcv = c; psv = s; }
                    else { hc[g >> 1] = f2_to_u32(pcv, c); hs[g >> 1] = f2_to_u32(psv, s); }
                    float cn = c * c1 - s * s1;
                    float sn = s * c1 + c * s1;
                    c = cn; s = sn;
                }
                #pragma unroll
                for (int j = 0; j < G / 8; j++) {
                    *(uint4*)(rowp + f * 2 * G + j * 8) =
                        make_uint4(hc[4 * j], hc[4 * j + 1], hc[4 * j + 2], hc[4 * j + 3]);
                    *(uint4*)(rowp + f * 2 * G + G + j * 8) =
                        make_uint4(hs[4 * j], hs[4 * j + 1], hs[4 * j + 2], hs[4 * j + 3]);
                }
            }
            // B tile: 64 rows x 64 halves = 512 uint4; 4 per thread
            __half* bdst = BtB + buf * BBUF_H;
            #pragma unroll
            for (int j = 0; j < 4; j++) {
                int q = tid + j * 128;
                int bk = q >> 3, bc = q & 7;
                *(uint4*)(bdst + bk * BST + bc * 8) =
                    *(const uint4*)(Bmat + (size_t)(pc * KCH + bk) * NOUT + o0 + bc * 8);
            }
            // prefetch seeds for chunk pc+1
            if (pc + 1 < NCHUNK) {
                #pragma unroll
                for (int f = 0; f < F; f++) {
                    curC[f] = Cseed[(size_t)((pc + 1) * F + f) * BATCH + n0 + m];
                    curS[f] = Sseed[(size_t)((pc + 1) * F + f) * BATCH + n0 + m];
                }
            }
            BAR_ARRIVE(FULL_BAR(buf));
        }
    } else {
        // ================= CONSUMER (threads 128..255) =================
        const int cw = wid - 4;                 // rows cw*32 .. cw*32+31
        const int m0 = cw * 32;
        const int gid = lane >> 2, tig = lane & 3;
        const int li = lane & 7, grp = lane >> 3;
        const uint32_t atB = smem_u32(AtB);
        const uint32_t btB = smem_u32(BtB);
        constexpr uint32_t ABUF_B = ABUF_H * 2;
        constexpr uint32_t BBUF_B = BBUF_H * 2;

        const uint32_t aRowL = lane & 15;       // A non-trans 16x16
        const uint32_t aColS = (lane >> 4) << 3;
        const uint32_t bRow = li + ((grp & 1) << 3);  // B trans
        const uint32_t bCol = ((grp >> 1) << 3);

        float acc[2][8][4];
        #pragma unroll
        for (int mt = 0; mt < 2; mt++)
            #pragma unroll
            for (int nt = 0; nt < 8; nt++)
                #pragma unroll
                for (int j = 0; j < 4; j++) acc[mt][nt][j] = 0.f;

        for (int t = 0; t < NCHUNK; t++) {
            const int buf = t & 1;
            BAR_WAIT(FULL_BAR(buf));
            const uint32_t aBase = atB + buf * ABUF_B;
            const uint32_t bBase = btB + buf * BBUF_B;
            #pragma unroll
            for (int ks = 0; ks < KCH; ks += 16) {
                uint32_t a[2][4], bb[4][4];
                #pragma unroll
                for (int mt = 0; mt < 2; mt++)
                    ldsm_x4(a[mt][0], a[mt][1], a[mt][2], a[mt][3],
                            aBase + ((m0 + mt * 16 + aRowL) * AST + ks + aColS) * 2);
                #pragma unroll
                for (int p = 0; p < 4; p++)
                    ldsm_x4_t(bb[p][0], bb[p][1], bb[p][2], bb[p][3],
                              bBase + ((ks + bRow) * BST + bCol + p * 16) * 2);
                #pragma unroll
                for (int mt = 0; mt < 2; mt++)
                    #pragma unroll
                    for (int nt = 0; nt < 8; nt++)
                        mma_fp16(acc[mt][nt][0], acc[mt][nt][1], acc[mt][nt][2], acc[mt][nt][3],
                                 a[mt][0], a[mt][1], a[mt][2], a[mt][3],
                                 bb[nt >> 1][(nt & 1) * 2], bb[nt >> 1][(nt & 1) * 2 + 1]);
            }
            BAR_ARRIVE(EMPTY_BAR(buf));
        }
        // epilogue
        #pragma unroll
        for (int mt = 0; mt < 2; mt++) {
            const int r0 = n0 + m0 + mt * 16 + gid;
            #pragma unroll
            for (int nt = 0; nt < 8; nt++) {
                const int col = o0 + nt * 8 + tig * 2;
                const float b0 = bias[col], b1 = bias[col + 1];
                float2 v0 = {acc[mt][nt][0] + b0, acc[mt][nt][1] + b1};
                float2 v1 = {acc[mt][nt][2] + b0, acc[mt][nt][3] + b1};
                *(float2*)&out[(size_t)r0 * NOUT + col] = v0;
                *(float2*)&out[(size_t)(r0 + 8) * NOUT + col] = v1;
            }
        }
    }
}

// ---------------- softmax over DOUT ----------------
__global__ void softmax_k(const float* __restrict__ in, float* __restrict__ out) {
    __shared__ float red[256];
    const int row = blockIdx.x, tid = threadIdx.x;
    float v = in[row * DOUT + tid];
    red[tid] = v;
    __syncthreads();
    for (int off = 128; off; off >>= 1) {
        if (tid < off) red[tid] = fmaxf(red[tid], red[tid + off]);
        __syncthreads();
    }
    float mx = red[0];
    __syncthreads();
    float e = expf(v - mx);
    red[tid] = e;
    __syncthreads();
    for (int off = 128; off; off >>= 1) {
        if (tid < off) red[tid] += red[tid + off];
        __syncthreads();
    }
    out[row * DOUT + tid] = e / red[0];
}

// ---------------- launch ----------------
// Launch order arranged so kan_ws<G2> is the 6th launch (ncu -s 5 -c 1 captures it).
extern "C" void kernel_launch(void* const* d_in, const int* in_sizes, int n_in,
                              void* d_out, int out_size) {
    const float* x       = (const float*)d_in[0];
    const float* W1      = (const float*)d_in[1];
    const float* b1      = (const float*)d_in[2];
    const float* gamma   = (const float*)d_in[3];
    const float* beta    = (const float*)d_in[4];
    const float* coeffs2 = (const float*)d_in[5];
    const float* bias2   = (const float*)d_in[6];
    const float* coeffs3 = (const float*)d_in[7];
    const float* bias3   = (const float*)d_in[8];
    float* out = (float*)d_out;

    float *pHpre, *pC1, *pS1, *pH2, *pC2, *pS2, *pH3;
    __half *pB2, *pB3;
    cudaGetSymbolAddress((void**)&pHpre, g_Hpre);
    cudaGetSymbolAddress((void**)&pC1, g_C1);
    cudaGetSymbolAddress((void**)&pS1, g_S1);
    cudaGetSymbolAddress((void**)&pH2, g_H2);
    cudaGetSymbolAddress((void**)&pC2, g_C2);
    cudaGetSymbolAddress((void**)&pS2, g_S2);
    cudaGetSymbolAddress((void**)&pB2, g_B2);
    cudaGetSymbolAddress((void**)&pB3, g_B3);
    cudaGetSymbolAddress((void**)&pH3, g_H3);

    const int smem_bytes = (2 * 128 * AST + 2 * KCH * BST) * 2;   // 55296
    cudaFuncSetAttribute(kan_ws<G2, H2DIM>, cudaFuncAttributeMaxDynamicSharedMemorySize, smem_bytes);
    cudaFuncSetAttribute(kan_ws<G3, DOUT>,  cudaFuncAttributeMaxDynamicSharedMemorySize, smem_bytes);

    // (1) layer 1
    gemm1<<<dim3(BATCH / 64, H1DIM / 64), 256>>>(x, W1, b1, pHpre);
    // (2,3) batchnorm stats (deterministic two-stage)
    reduce_stats<<<256, 256>>>();
    finalize_stats<<<1, 256>>>(gamma, beta);
    // (4) layer-2 seeds (BN+ReLU fused)
    basis_seed<<<dim3(H1DIM / 32, BATCH / 32), dim3(32, 8)>>>(pHpre, pC1, pS1, 1);
    // (5) layer-2 coeff transform
    transpose_coeffs<<<dim3((512 * G2) / 32, H2DIM / 32, 2), dim3(32, 8)>>>(coeffs2, pB2, H2DIM, H1DIM, G2);
    // (6) layer-2 KAN GEMM  <-- profiled launch
    kan_ws<G2, H2DIM><<<dim3(BATCH / 128, H2DIM / 64), 256, smem_bytes>>>(pC1, pS1, pB2, bias2, pH2);
    // (7) layer-3 coeff transform
    transpose_coeffs<<<dim3((512 * G3) / 32, DOUT / 32, 2), dim3(32, 8)>>>(coeffs3, pB3, DOUT, H2DIM, G3);
    // (8) layer-3 seeds (identity)
    basis_seed<<<dim3(H2DIM / 32, BATCH / 32), dim3(32, 8)>>>(pH2, pC2, pS2, 0);
    // (9) layer-3 KAN GEMM
    kan_ws<G3, DOUT><<<dim3(BATCH / 128, DOUT / 64), 256, smem_bytes>>>(pC2, pS2, pB3, bias3, pH3);
    // (10) softmax
    softmax_k<<<BATCH, 256>>>(pH3, out);
}